// round 2
// baseline (speedup 1.0000x reference)
#include <cuda_runtime.h>
#include <mma.h>
#include <cstdint>
#include <cstddef>

using namespace nvcuda;

#define NMAX   100000
#define EMAX   700000
#define TEDGE  7
#define COUT   256

// ---------------- scratch (device globals; no allocation allowed) ----------------
__device__ float g_seg[(size_t)NMAX * TEDGE * COUT];   // 716.8 MB: segment sums (conv-a uses C=128 view)
__device__ float g_cnt[NMAX * TEDGE];                  // per-(node,etype) edge counts
__device__ float g_y1 [(size_t)NMAX * COUT];           // conv-a GEMM output (pre-BN)
__device__ float g_y2 [(size_t)NMAX * COUT];           // conv-b GEMM output (pre-BN)
__device__ float g_sc [(size_t)NMAX * COUT];           // shortcut GEMM output (pre-BN)
__device__ float g_stats[6 * 256];                     // col sums / sumsq for y1,y2,sc
__device__ float g_bn   [4 * 256];                     // fused BN scale/bias slots

// ---------------- helpers ----------------
__device__ __forceinline__ void red_add4(float* p, float4 v) {
    asm volatile("red.global.add.v4.f32 [%0], {%1,%2,%3,%4};"
                 :: "l"(p), "f"(v.x), "f"(v.y), "f"(v.z), "f"(v.w) : "memory");
}

__global__ void zero_kernel(float* __restrict__ p, long n4) {
    long i = (long)blockIdx.x * blockDim.x + threadIdx.x;
    long s = (long)gridDim.x * blockDim.x;
    float4 z = make_float4(0.f, 0.f, 0.f, 0.f);
    float4* p4 = (float4*)p;
    for (long j = i; j < n4; j += s) p4[j] = z;
}

// ---------------- scatter: conv-a (gather x[col], C=128) ----------------
__global__ void scatter_a_kernel(const float* __restrict__ x,
                                 const int* __restrict__ row, const int* __restrict__ col,
                                 const int* __restrict__ et, int E)
{
    int w    = (blockIdx.x * blockDim.x + threadIdx.x) >> 5;
    int lane = threadIdx.x & 31;
    if (w >= E) return;
    int r = __ldg(row + w), c = __ldg(col + w), t = __ldg(et + w);
    size_t idx = (size_t)r * TEDGE + (size_t)t;
    float4 v = *(const float4*)(x + (size_t)c * 128 + lane * 4);
    red_add4(g_seg + idx * 128 + lane * 4, v);
    if (lane == 0) atomicAdd(g_cnt + idx, 1.0f);
}

// ---------------- scatter: conv-b (gather relu(bn(y1))[col], C=256; BN fused) ----------------
__global__ void scatter_b_kernel(const float* __restrict__ y1,
                                 const int* __restrict__ row, const int* __restrict__ col,
                                 const int* __restrict__ et,
                                 const float* __restrict__ bnscale,
                                 const float* __restrict__ bnbias, int E)
{
    int w    = (blockIdx.x * blockDim.x + threadIdx.x) >> 5;
    int lane = threadIdx.x & 31;
    if (w >= E) return;
    int r = __ldg(row + w), c = __ldg(col + w), t = __ldg(et + w);
    size_t idx = (size_t)r * TEDGE + (size_t)t;
#pragma unroll
    for (int h = 0; h < 2; h++) {
        int off = h * 128 + lane * 4;
        float4 v = *(const float4*)(y1 + (size_t)c * 256 + off);
        float4 s = *(const float4*)(bnscale + off);
        float4 b = *(const float4*)(bnbias  + off);
        float4 o;
        o.x = fmaxf(fmaf(v.x, s.x, b.x), 0.f);
        o.y = fmaxf(fmaf(v.y, s.y, b.y), 0.f);
        o.z = fmaxf(fmaf(v.z, s.z, b.z), 0.f);
        o.w = fmaxf(fmaf(v.w, s.w, b.w), 0.f);
        red_add4(g_seg + idx * 256 + off, o);
    }
}

// ---------------- tf32 wmma GEMM: Out[M,256] = A[M,K] (optionally /cnt) @ B[K,256] ----------------
// BM=128, BN=256 (full), BK=16. 8 warps (2 along M x 4 along N), warp tile 64x64.
// A divide-by-count fused into the A-tile load (mean = seg / max(cnt,1)).
#define LDA 20
#define LDB 260

template<bool DIV>
__global__ void __launch_bounds__(256)
gemm256(const float* __restrict__ A, const float* __restrict__ B,
        const float* __restrict__ cnt, float* __restrict__ Out,
        int M, int K, int Cchan)
{
    extern __shared__ float sh[];
    float* As = sh;                  // [2][128*LDA]
    float* Bs = sh + 2 * 128 * LDA;  // [2][16*LDB]

    const int tid  = threadIdx.x;
    const int wid  = tid >> 5;
    const int lane = tid & 31;
    const int wm   = wid & 1;    // 0..1 (M)
    const int wn   = wid >> 1;   // 0..3 (N)
    const int mBase = blockIdx.x * 128;

    wmma::fragment<wmma::accumulator, 16, 16, 8, float> cf[4][4];
#pragma unroll
    for (int i = 0; i < 4; i++)
#pragma unroll
        for (int j = 0; j < 4; j++) wmma::fill_fragment(cf[i][j], 0.0f);

    float4 ra[2], rb[4];

    auto ldA = [&](int kk) {
#pragma unroll
        for (int it = 0; it < 2; it++) {
            int f  = tid + it * 256;       // 0..511 float4s of the 128x16 tile
            int rr = f >> 2;
            int c4 = (f & 3) << 2;
            int gm = mBase + rr;
            float4 v = make_float4(0.f, 0.f, 0.f, 0.f);
            if (gm < M) {
                v = *(const float4*)(A + (size_t)gm * K + kk + c4);
                if (DIV) {
                    float ct  = __ldg(cnt + gm * TEDGE + (kk + c4) / Cchan);
                    float inv = 1.0f / fmaxf(ct, 1.0f);
                    v.x *= inv; v.y *= inv; v.z *= inv; v.w *= inv;
                }
            }
            ra[it] = v;
        }
    };
    auto ldB = [&](int kk) {
#pragma unroll
        for (int it = 0; it < 4; it++) {
            int f  = tid + it * 256;       // 0..1023 float4s of the 16x256 tile
            int rr = f >> 6;
            int c4 = (f & 63) << 2;
            rb[it] = *(const float4*)(B + (size_t)(kk + rr) * 256 + c4);
        }
    };
    auto stTiles = [&](int buf) {
        float* as = As + buf * (128 * LDA);
        float* bs = Bs + buf * (16 * LDB);
#pragma unroll
        for (int it = 0; it < 2; it++) {
            int f  = tid + it * 256;
            int rr = f >> 2;
            int c4 = (f & 3) << 2;
            *(float4*)(as + rr * LDA + c4) = ra[it];
        }
#pragma unroll
        for (int it = 0; it < 4; it++) {
            int f  = tid + it * 256;
            int rr = f >> 6;
            int c4 = (f & 63) << 2;
            *(float4*)(bs + rr * LDB + c4) = rb[it];
        }
    };

    ldA(0); ldB(0);
    stTiles(0);
    __syncthreads();

    const int nk = K >> 4;
    for (int t = 0; t < nk; t++) {
        int cur = t & 1;
        if (t + 1 < nk) { ldA((t + 1) << 4); ldB((t + 1) << 4); }  // overlap gmem with mma

        const float* as = As + cur * (128 * LDA) + (wm * 64) * LDA;
        const float* bs = Bs + cur * (16 * LDB) + wn * 64;
#pragma unroll
        for (int ks = 0; ks < 16; ks += 8) {
            wmma::fragment<wmma::matrix_a, 16, 16, 8, wmma::precision::tf32, wmma::row_major> af[4];
            wmma::fragment<wmma::matrix_b, 16, 16, 8, wmma::precision::tf32, wmma::row_major> bf[4];
#pragma unroll
            for (int i = 0; i < 4; i++) {
                wmma::load_matrix_sync(af[i], as + (i * 16) * LDA + ks, LDA);
#pragma unroll
                for (int e = 0; e < af[i].num_elements; e++)
                    af[i].x[e] = wmma::__float_to_tf32(af[i].x[e]);
            }
#pragma unroll
            for (int j = 0; j < 4; j++) {
                wmma::load_matrix_sync(bf[j], bs + ks * LDB + j * 16, LDB);
#pragma unroll
                for (int e = 0; e < bf[j].num_elements; e++)
                    bf[j].x[e] = wmma::__float_to_tf32(bf[j].x[e]);
            }
#pragma unroll
            for (int i = 0; i < 4; i++)
#pragma unroll
                for (int j = 0; j < 4; j++)
                    wmma::mma_sync(cf[i][j], af[i], bf[j], cf[i][j]);
        }
        __syncthreads();
        if (t + 1 < nk) { stTiles(cur ^ 1); __syncthreads(); }
    }

    // epilogue
    int mw = mBase + wm * 64;
    int nw = wn * 64;
    if (mBase + 128 <= M) {
#pragma unroll
        for (int i = 0; i < 4; i++)
#pragma unroll
            for (int j = 0; j < 4; j++)
                wmma::store_matrix_sync(Out + (size_t)(mw + i * 16) * 256 + nw + j * 16,
                                        cf[i][j], 256, wmma::mem_row_major);
    } else {
        __shared__ float patch[8][264];
#pragma unroll
        for (int i = 0; i < 4; i++)
#pragma unroll
            for (int j = 0; j < 4; j++) {
                wmma::store_matrix_sync(&patch[wid][0], cf[i][j], 16, wmma::mem_row_major);
                __syncwarp();
                for (int e = lane; e < 256; e += 32) {
                    int rr = e >> 4, cc = e & 15;
                    int gm = mw + i * 16 + rr;
                    if (gm < M) Out[(size_t)gm * 256 + nw + j * 16 + cc] = patch[wid][e];
                }
                __syncwarp();
            }
    }
}

// ---------------- column stats (sum, sumsq over rows) ----------------
__global__ void colstats_kernel(const float* __restrict__ A, int N,
                                float* __restrict__ s, float* __restrict__ q)
{
    int c = threadIdx.x;   // 256 columns
    float sum = 0.f, sq = 0.f;
    for (int r = blockIdx.x; r < N; r += gridDim.x) {
        float v = A[(size_t)r * 256 + c];
        sum += v; sq += v * v;
    }
    atomicAdd(s + c, sum);
    atomicAdd(q + c, sq);
}

__global__ void finalize_bn_kernel(const float* __restrict__ gamma, const float* __restrict__ beta,
                                   float invN, const float* __restrict__ sum, const float* __restrict__ sq,
                                   float* __restrict__ scale, float* __restrict__ bias)
{
    int c = threadIdx.x;
    float m    = sum[c] * invN;
    float var  = sq[c] * invN - m * m;
    float rstd = rsqrtf(var + 1e-5f);
    float s    = gamma[c] * rstd;
    scale[c] = s;
    bias[c]  = beta[c] - m * s;
}

// ---------------- final: out = relu(bn(y2) + bn(sc)) ----------------
__global__ void final_kernel(const float4* __restrict__ y2, const float4* __restrict__ sc,
                             const float* __restrict__ bn, float4* __restrict__ out, int n4)
{
    int i = blockIdx.x * blockDim.x + threadIdx.x;
    if (i >= n4) return;
    int c = i & 63;    // float4 column index within the 256-wide row
    float4 a = y2[i], b = sc[i];
    float4 S2 = ((const float4*)(bn      ))[c];
    float4 B2 = ((const float4*)(bn + 256))[c];
    float4 SS = ((const float4*)(bn + 512))[c];
    float4 SB = ((const float4*)(bn + 768))[c];
    float4 r;
    r.x = fmaxf(fmaf(a.x, S2.x, B2.x) + fmaf(b.x, SS.x, SB.x), 0.f);
    r.y = fmaxf(fmaf(a.y, S2.y, B2.y) + fmaf(b.y, SS.y, SB.y), 0.f);
    r.z = fmaxf(fmaf(a.z, S2.z, B2.z) + fmaf(b.z, SS.z, SB.z), 0.f);
    r.w = fmaxf(fmaf(a.w, S2.w, B2.w) + fmaf(b.w, SS.w, SB.w), 0.f);
    out[i] = r;
}

// ---------------- launch ----------------
extern "C" void kernel_launch(void* const* d_in, const int* in_sizes, int n_in,
                              void* d_out, int out_size)
{
    const float* x  = (const float*)d_in[0];
    const int*   ei = (const int*)  d_in[1];
    const int*   et = (const int*)  d_in[2];
    // d_in[3] = node_type (unused: n_node_type == 0 path)
    const float* Wa = (const float*)d_in[4];
    const float* ga = (const float*)d_in[5];
    const float* ba = (const float*)d_in[6];
    const float* Wb = (const float*)d_in[7];
    const float* gb = (const float*)d_in[8];
    const float* bb = (const float*)d_in[9];
    const float* W1 = (const float*)d_in[10];
    const float* g1 = (const float*)d_in[11];
    const float* b1 = (const float*)d_in[12];

    const int N = in_sizes[0] / 128;
    const int E = in_sizes[1] / 2;
    const int* row = ei;
    const int* col = ei + E;
    float* out = (float*)d_out;

    float *seg, *cnt, *y1, *y2, *sc, *stats, *bn;
    cudaGetSymbolAddress((void**)&seg,   g_seg);
    cudaGetSymbolAddress((void**)&cnt,   g_cnt);
    cudaGetSymbolAddress((void**)&y1,    g_y1);
    cudaGetSymbolAddress((void**)&y2,    g_y2);
    cudaGetSymbolAddress((void**)&sc,    g_sc);
    cudaGetSymbolAddress((void**)&stats, g_stats);
    cudaGetSymbolAddress((void**)&bn,    g_bn);

    const size_t shmem = (size_t)(2 * 128 * LDA + 2 * 16 * LDB) * sizeof(float); // 53760 B
    cudaFuncSetAttribute(gemm256<true>,  cudaFuncAttributeMaxDynamicSharedMemorySize, (int)shmem);
    cudaFuncSetAttribute(gemm256<false>, cudaFuncAttributeMaxDynamicSharedMemorySize, (int)shmem);

    const float invN = 1.0f / (float)N;
    const int sblocks = (E * 32 + 255) / 256;
    const int gblocks = (N + 127) / 128;

    // ---- phase A: conv-a ----
    zero_kernel<<<2048, 256>>>(seg,   (long)N * TEDGE * 128 / 4);
    zero_kernel<<<64,   256>>>(cnt,   (long)N * TEDGE / 4);
    zero_kernel<<<2,    256>>>(stats, (6 * 256) / 4);

    scatter_a_kernel<<<sblocks, 256>>>(x, row, col, et, E);
    gemm256<true><<<gblocks, 256, shmem>>>(seg, Wa, cnt, y1, N, TEDGE * 128, 128);

    colstats_kernel<<<512, 256>>>(y1, N, stats, stats + 256);
    finalize_bn_kernel<<<1, 256>>>(ga, ba, invN, stats, stats + 256, bn, bn + 256);

    // ---- phase B: conv-b (BN+ReLU of y1 fused into gather) ----
    zero_kernel<<<4096, 256>>>(seg, (long)N * TEDGE * 256 / 4);
    scatter_b_kernel<<<sblocks, 256>>>(y1, row, col, et, bn, bn + 256, E);

    gemm256<true><<<gblocks, 256, shmem>>>(seg, Wb, cnt, y2, N, TEDGE * 256, 256);
    gemm256<false><<<gblocks, 256, shmem>>>(x, W1, nullptr, sc, N, 128, 1);

    colstats_kernel<<<512, 256>>>(y2, N, stats + 512,  stats + 768);
    colstats_kernel<<<512, 256>>>(sc, N, stats + 1024, stats + 1280);
    finalize_bn_kernel<<<1, 256>>>(gb, bb, invN, stats + 512,  stats + 768,  bn,       bn + 256);
    finalize_bn_kernel<<<1, 256>>>(g1, b1, invN, stats + 1024, stats + 1280, bn + 512, bn + 768);

    const int n4 = out_size / 4;
    final_kernel<<<(n4 + 255) / 256, 256>>>((const float4*)y2, (const float4*)sc, bn, (float4*)out, n4);
}

// round 4
// speedup vs baseline: 1.4544x; 1.4544x over previous
#include <cuda_runtime.h>
#include <cstdint>
#include <cstddef>

#define TEDGE  7
#define NMAX   100000
#define COUT   256

// ---------------- scratch (device globals; no allocation allowed) ----------------
__device__ float g_seg[(size_t)NMAX * TEDGE * COUT];   // segment sums (conv-a uses C=128 view)
__device__ float g_cnt[NMAX * TEDGE];                  // per-(node,etype) edge counts
__device__ float g_y1 [(size_t)NMAX * COUT];
__device__ float g_y2 [(size_t)NMAX * COUT];
__device__ float g_sc [(size_t)NMAX * COUT];
__device__ float g_bt [1792 * 256];                    // W transposed to [N][K] tiles, tf32-rounded
__device__ float g_stats[6 * 256];
__device__ float g_bn   [4 * 256];

// ---------------- helpers ----------------
__device__ __forceinline__ uint32_t f2tf32(float x) {
    uint32_t u; asm("cvt.rn.tf32.f32 %0, %1;" : "=r"(u) : "f"(x)); return u;
}
__device__ __forceinline__ void red_add4(float* p, float4 v) {
    asm volatile("red.global.add.v4.f32 [%0], {%1,%2,%3,%4};"
                 :: "l"(p), "f"(v.x), "f"(v.y), "f"(v.z), "f"(v.w) : "memory");
}
__device__ __forceinline__ void cp_async16(uint32_t dst, const void* src) {
    asm volatile("cp.async.ca.shared.global [%0], [%1], 16;" :: "r"(dst), "l"(src) : "memory");
}
#define CP_COMMIT() asm volatile("cp.async.commit_group;" ::: "memory")
#define CP_WAIT0()  asm volatile("cp.async.wait_group 0;" ::: "memory")

__global__ void zero_kernel(float* __restrict__ p, long n4) {
    long i = (long)blockIdx.x * blockDim.x + threadIdx.x;
    long s = (long)gridDim.x * blockDim.x;
    float4 z = make_float4(0.f, 0.f, 0.f, 0.f);
    float4* p4 = (float4*)p;
    for (long j = i; j < n4; j += s) p4[j] = z;
}

// ---------------- scatters ----------------
__global__ void scatter_a_kernel(const float* __restrict__ x,
                                 const int* __restrict__ row, const int* __restrict__ col,
                                 const int* __restrict__ et, int E)
{
    int w    = (blockIdx.x * blockDim.x + threadIdx.x) >> 5;
    int lane = threadIdx.x & 31;
    if (w >= E) return;
    int r = __ldg(row + w), c = __ldg(col + w), t = __ldg(et + w);
    size_t idx = (size_t)r * TEDGE + (size_t)t;
    float4 v = *(const float4*)(x + (size_t)c * 128 + lane * 4);
    red_add4(g_seg + idx * 128 + lane * 4, v);
    if (lane == 0) atomicAdd(g_cnt + idx, 1.0f);
}

__global__ void scatter_b_kernel(const float* __restrict__ y1,
                                 const int* __restrict__ row, const int* __restrict__ col,
                                 const int* __restrict__ et,
                                 const float* __restrict__ bnscale,
                                 const float* __restrict__ bnbias, int E)
{
    int w    = (blockIdx.x * blockDim.x + threadIdx.x) >> 5;
    int lane = threadIdx.x & 31;
    if (w >= E) return;
    int r = __ldg(row + w), c = __ldg(col + w), t = __ldg(et + w);
    size_t idx = (size_t)r * TEDGE + (size_t)t;
#pragma unroll
    for (int h = 0; h < 2; h++) {
        int off = h * 128 + lane * 4;
        float4 v = *(const float4*)(y1 + (size_t)c * 256 + off);
        float4 s = *(const float4*)(bnscale + off);
        float4 b = *(const float4*)(bnbias  + off);
        float4 o;
        o.x = fmaxf(fmaf(v.x, s.x, b.x), 0.f);
        o.y = fmaxf(fmaf(v.y, s.y, b.y), 0.f);
        o.z = fmaxf(fmaf(v.z, s.z, b.z), 0.f);
        o.w = fmaxf(fmaf(v.w, s.w, b.w), 0.f);
        red_add4(g_seg + idx * 256 + off, o);
    }
}

// ---------------- W transpose: W[K,256] -> Bt tiles [kblk][n 0..255][kc 0..31], tf32 RN ----------------
__global__ void transpose_w(const float* __restrict__ W, float* __restrict__ Bt, int K) {
    int i = blockIdx.x * blockDim.x + threadIdx.x;
    if (i >= K * 256) return;
    int k = i >> 8, n = i & 255;
    ((uint32_t*)Bt)[(size_t)(k >> 5) * 8192 + n * 32 + (k & 31)] = f2tf32(W[i]);
}

// ---------------- mma.sync tf32 GEMM ----------------
// Out[M,256] = (A[M,K] (/cnt)) @ W[K,256].  BM=128, BN=128, BK=32.
// 256 threads = 8 warps, 4(M) x 2(N), warp tile 32x64 of m16n8k8 tiles.
// Smem rows padded to 36 floats -> conflict-free scalar LDS for fragments.
// grid.x = 2 * mtiles; nb = bid & 1 (adjacent CTAs share the A tile via L2).
#define LDS_PAD 36
#define ABUF    (128 * LDS_PAD)          // 4608 floats per buffer

__device__ __forceinline__ void mma_tf32(float* c, const uint32_t* a, const uint32_t* b) {
    asm volatile("mma.sync.aligned.m16n8k8.row.col.f32.tf32.tf32.f32 "
                 "{%0,%1,%2,%3}, {%4,%5,%6,%7}, {%8,%9}, {%0,%1,%2,%3};"
                 : "+f"(c[0]), "+f"(c[1]), "+f"(c[2]), "+f"(c[3])
                 : "r"(a[0]), "r"(a[1]), "r"(a[2]), "r"(a[3]), "r"(b[0]), "r"(b[1]));
}

template<bool DIV>
__global__ void __launch_bounds__(256, 2)
gemm_mma(const float* __restrict__ A, const float* __restrict__ Bt,
         const float* __restrict__ cnt, float* __restrict__ Out,
         int M, int K, int Cchan)
{
    extern __shared__ float sh[];
    // layout: A0 [0,4608) A1 [4608,9216) B0 [9216,13824) B1 [13824,18432)

    const int tid  = threadIdx.x;
    const int wid  = tid >> 5;
    const int lane = tid & 31;
    const int g    = lane >> 2;       // 0..7
    const int tg   = lane & 3;        // 0..3
    const int wm   = wid >> 1;        // 0..3
    const int wn   = wid & 1;         // 0..1
    const int nb     = blockIdx.x & 1;
    const int mBase  = (blockIdx.x >> 1) * 128;

    float c[2][8][4];
#pragma unroll
    for (int mi = 0; mi < 2; mi++)
#pragma unroll
        for (int ni = 0; ni < 8; ni++)
#pragma unroll
            for (int q = 0; q < 4; q++) c[mi][ni][q] = 0.f;

    uint32_t ra[4][4];  // prefetched A (tf32-rounded bits), 4 float4 per thread

    auto ldA = [&](int kk) {
#pragma unroll
        for (int it = 0; it < 4; it++) {
            int f  = tid + it * 256;          // 0..1023
            int m  = f >> 3;
            int c4 = f & 7;
            int gm = mBase + m;
            float4 v = make_float4(0.f, 0.f, 0.f, 0.f);
            if (gm < M) {
                v = *(const float4*)(A + (size_t)gm * K + kk + c4 * 4);
                if (DIV) {
                    float ct  = __ldg(cnt + gm * TEDGE + kk / Cchan);
                    float inv = 1.0f / fmaxf(ct, 1.0f);
                    v.x *= inv; v.y *= inv; v.z *= inv; v.w *= inv;
                }
            }
            ra[it][0] = f2tf32(v.x); ra[it][1] = f2tf32(v.y);
            ra[it][2] = f2tf32(v.z); ra[it][3] = f2tf32(v.w);
        }
    };
    auto stA = [&](int buf) {
        float* as = sh + buf * ABUF;
#pragma unroll
        for (int it = 0; it < 4; it++) {
            int f  = tid + it * 256;
            int m  = f >> 3;
            int c4 = f & 7;
            *(uint4*)(as + m * LDS_PAD + c4 * 4) = *(uint4*)ra[it];
        }
    };
    auto cpB = [&](int kblk, int buf) {
        float* bs = sh + 2 * ABUF + buf * ABUF;
        const float* src = Bt + (size_t)kblk * 8192 + nb * 128 * 32;
#pragma unroll
        for (int it = 0; it < 4; it++) {
            int f  = tid + it * 256;          // 0..1023
            int n  = f >> 3;
            int c4 = f & 7;
            uint32_t dst = (uint32_t)__cvta_generic_to_shared(bs + n * LDS_PAD + c4 * 4);
            cp_async16(dst, src + n * 32 + c4 * 4);
        }
    };

    const int nk = K >> 5;

    ldA(0);
    cpB(0, 0); CP_COMMIT();
    stA(0);
    CP_WAIT0(); __syncthreads();

    for (int t = 0; t < nk; t++) {
        const int cur = t & 1;
        if (t + 1 < nk) {
            ldA((t + 1) << 5);
            cpB(t + 1, cur ^ 1); CP_COMMIT();
        }

        const float* As = sh + cur * ABUF;
        const float* Bs = sh + 2 * ABUF + cur * ABUF;
        const int rbase = wm * 32;
        const int nbase = wn * 64;
#pragma unroll
        for (int ks = 0; ks < 32; ks += 8) {
            uint32_t a[2][4];
#pragma unroll
            for (int mi = 0; mi < 2; mi++) {
                int r = rbase + mi * 16 + g;
                a[mi][0] = __float_as_uint(As[r * LDS_PAD + ks + tg]);
                a[mi][1] = __float_as_uint(As[(r + 8) * LDS_PAD + ks + tg]);
                a[mi][2] = __float_as_uint(As[r * LDS_PAD + ks + tg + 4]);
                a[mi][3] = __float_as_uint(As[(r + 8) * LDS_PAD + ks + tg + 4]);
            }
            uint32_t b[8][2];
#pragma unroll
            for (int ni = 0; ni < 8; ni++) {
                int n = nbase + ni * 8 + g;
                b[ni][0] = __float_as_uint(Bs[n * LDS_PAD + ks + tg]);
                b[ni][1] = __float_as_uint(Bs[n * LDS_PAD + ks + tg + 4]);
            }
#pragma unroll
            for (int mi = 0; mi < 2; mi++)
#pragma unroll
                for (int ni = 0; ni < 8; ni++)
                    mma_tf32(c[mi][ni], a[mi], b[ni]);
        }

        if (t + 1 < nk) {
            __syncthreads();      // everyone done reading buf cur^1 from 2 iters ago
            stA(cur ^ 1);
            CP_WAIT0();
            __syncthreads();
        }
    }

    // epilogue: float2 stores
    const int colBase = nb * 128 + wn * 64;
#pragma unroll
    for (int mi = 0; mi < 2; mi++) {
        int r0 = mBase + wm * 32 + mi * 16 + g;
        int r1 = r0 + 8;
#pragma unroll
        for (int ni = 0; ni < 8; ni++) {
            int colw = colBase + ni * 8 + 2 * tg;
            if (r0 < M) *(float2*)(Out + (size_t)r0 * 256 + colw) = make_float2(c[mi][ni][0], c[mi][ni][1]);
            if (r1 < M) *(float2*)(Out + (size_t)r1 * 256 + colw) = make_float2(c[mi][ni][2], c[mi][ni][3]);
        }
    }
}

// ---------------- column stats ----------------
__global__ void colstats_kernel(const float* __restrict__ A, int N,
                                float* __restrict__ s, float* __restrict__ q)
{
    int c = threadIdx.x;
    float sum = 0.f, sq = 0.f;
    for (int r = blockIdx.x; r < N; r += gridDim.x) {
        float v = A[(size_t)r * 256 + c];
        sum += v; sq += v * v;
    }
    atomicAdd(s + c, sum);
    atomicAdd(q + c, sq);
}

__global__ void finalize_bn_kernel(const float* __restrict__ gamma, const float* __restrict__ beta,
                                   float invN, const float* __restrict__ sum, const float* __restrict__ sq,
                                   float* __restrict__ scale, float* __restrict__ bias)
{
    int c = threadIdx.x;
    float m    = sum[c] * invN;
    float var  = sq[c] * invN - m * m;
    float rstd = rsqrtf(var + 1e-5f);
    float s    = gamma[c] * rstd;
    scale[c] = s;
    bias[c]  = beta[c] - m * s;
}

// ---------------- final: out = relu(bn(y2) + bn(sc)) ----------------
__global__ void final_kernel(const float4* __restrict__ y2, const float4* __restrict__ sc,
                             const float* __restrict__ bn, float4* __restrict__ out, int n4)
{
    int i = blockIdx.x * blockDim.x + threadIdx.x;
    if (i >= n4) return;
    int c = i & 63;
    float4 a = y2[i], b = sc[i];
    float4 S2 = ((const float4*)(bn      ))[c];
    float4 B2 = ((const float4*)(bn + 256))[c];
    float4 SS = ((const float4*)(bn + 512))[c];
    float4 SB = ((const float4*)(bn + 768))[c];
    float4 r;
    r.x = fmaxf(fmaf(a.x, S2.x, B2.x) + fmaf(b.x, SS.x, SB.x), 0.f);
    r.y = fmaxf(fmaf(a.y, S2.y, B2.y) + fmaf(b.y, SS.y, SB.y), 0.f);
    r.z = fmaxf(fmaf(a.z, S2.z, B2.z) + fmaf(b.z, SS.z, SB.z), 0.f);
    r.w = fmaxf(fmaf(a.w, S2.w, B2.w) + fmaf(b.w, SS.w, SB.w), 0.f);
    out[i] = r;
}

// ---------------- launch ----------------
extern "C" void kernel_launch(void* const* d_in, const int* in_sizes, int n_in,
                              void* d_out, int out_size)
{
    const float* x  = (const float*)d_in[0];
    const int*   ei = (const int*)  d_in[1];
    const int*   et = (const int*)  d_in[2];
    const float* Wa = (const float*)d_in[4];
    const float* ga = (const float*)d_in[5];
    const float* ba = (const float*)d_in[6];
    const float* Wb = (const float*)d_in[7];
    const float* gb = (const float*)d_in[8];
    const float* bb = (const float*)d_in[9];
    const float* W1 = (const float*)d_in[10];
    const float* g1 = (const float*)d_in[11];
    const float* b1 = (const float*)d_in[12];

    const int N = in_sizes[0] / 128;
    const int E = in_sizes[1] / 2;
    const int* row = ei;
    const int* col = ei + E;
    float* out = (float*)d_out;

    float *seg, *cnt, *y1, *y2, *sc, *bt, *stats, *bn;
    cudaGetSymbolAddress((void**)&seg,   g_seg);
    cudaGetSymbolAddress((void**)&cnt,   g_cnt);
    cudaGetSymbolAddress((void**)&y1,    g_y1);
    cudaGetSymbolAddress((void**)&y2,    g_y2);
    cudaGetSymbolAddress((void**)&sc,    g_sc);
    cudaGetSymbolAddress((void**)&bt,    g_bt);
    cudaGetSymbolAddress((void**)&stats, g_stats);
    cudaGetSymbolAddress((void**)&bn,    g_bn);

    const int shbytes = 4 * ABUF * sizeof(float);  // 73728
    cudaFuncSetAttribute(gemm_mma<true>,  cudaFuncAttributeMaxDynamicSharedMemorySize, shbytes);
    cudaFuncSetAttribute(gemm_mma<false>, cudaFuncAttributeMaxDynamicSharedMemorySize, shbytes);

    const float invN = 1.0f / (float)N;
    const int sblocks = (E * 32 + 255) / 256;
    const int gblocks = 2 * ((N + 127) / 128);

    // ---- phase A: conv-a ----
    zero_kernel<<<2048, 256>>>(seg,   (long)N * TEDGE * 128 / 4);
    zero_kernel<<<64,   256>>>(cnt,   (long)N * TEDGE / 4);
    zero_kernel<<<2,    256>>>(stats, (6 * 256) / 4);
    transpose_w<<<(896 * 256 + 255) / 256, 256>>>(Wa, bt, 896);

    scatter_a_kernel<<<sblocks, 256>>>(x, row, col, et, E);
    gemm_mma<true><<<gblocks, 256, shbytes>>>(seg, bt, cnt, y1, N, TEDGE * 128, 128);

    colstats_kernel<<<512, 256>>>(y1, N, stats, stats + 256);
    finalize_bn_kernel<<<1, 256>>>(ga, ba, invN, stats, stats + 256, bn, bn + 256);

    // ---- phase B: conv-b (BN+ReLU of y1 fused into gather) ----
    zero_kernel<<<4096, 256>>>(seg, (long)N * TEDGE * 256 / 4);
    transpose_w<<<(1792 * 256 + 255) / 256, 256>>>(Wb, bt, 1792);
    scatter_b_kernel<<<sblocks, 256>>>(y1, row, col, et, bn, bn + 256, E);

    gemm_mma<true><<<gblocks, 256, shbytes>>>(seg, bt, cnt, y2, N, TEDGE * 256, 256);

    transpose_w<<<(128 * 256 + 255) / 256, 256>>>(W1, bt, 128);
    gemm_mma<false><<<gblocks, 256, shbytes>>>(x, bt, nullptr, sc, N, 128, 1);

    colstats_kernel<<<512, 256>>>(y2, N, stats + 512,  stats + 768);
    colstats_kernel<<<512, 256>>>(sc, N, stats + 1024, stats + 1280);
    finalize_bn_kernel<<<1, 256>>>(gb, bb, invN, stats + 512,  stats + 768,  bn,       bn + 256);
    finalize_bn_kernel<<<1, 256>>>(g1, b1, invN, stats + 1024, stats + 1280, bn + 512, bn + 768);

    const int n4 = out_size / 4;
    final_kernel<<<(n4 + 255) / 256, 256>>>((const float4*)y2, (const float4*)sc, bn, (float4*)out, n4);
}